// round 15
// baseline (speedup 1.0000x reference)
#include <cuda_runtime.h>
#include <cuda_fp16.h>
#include <cuda_bf16.h>
#include <mma.h>
#include <stdint.h>

using namespace nvcuda;

// Problem constants
#define BB 8
#define NN 10000
#define FF 256
#define HH 128
#define EE 320000
#define MTOT (BB * NN)       // 80000 rows
#define ETOT (BB * EE)       // 2,560,000 edges

// bucket geometry: fixed capacity per row (Poisson(32) -> P(>128) ~ 1e-35)
#define CAP 128
// bucket kernel: 10 edges/thread, 256 threads, 125 blocks per batch
#define EPT 10
#define BPB 125              // EE / (256*EPT) = 125 exactly

// -------- device scratch (no allocations allowed) --------
__device__ __half        g_xwh[(size_t)MTOT * HH];   // dropout(x)@W in fp16, 20.5 MB
__device__ int           g_fill[MTOT];               // per-row edge count
__device__ int2          g_edge[(size_t)MTOT * CAP]; // fixed-capacity buckets, 82 MB
__device__ __nv_bfloat16 g_whi[FF * HH];             // W hi split (bf16)
__device__ __nv_bfloat16 g_wlo[FF * HH];             // W lo split (bf16)
__device__ int           g_is32;                     // 1 if rows/cols int32, 0 if int64

// ---------------------------------------------------------
// Index dtype detection: int64 data has all-zero odd 32-bit words
// ---------------------------------------------------------
__global__ void detect_kernel(const void* __restrict__ rows) {
    const unsigned* p = (const unsigned*)rows;
    unsigned acc = 0;
    for (int i = threadIdx.x; i < 2048; i += 32)
        acc |= p[2 * i + 1];
#pragma unroll
    for (int o = 16; o; o >>= 1) acc |= __shfl_xor_sync(0xffffffffu, acc, o);
    if (threadIdx.x == 0) g_is32 = (acc != 0);
}

__device__ __forceinline__ int load_idx(const void* p, int i, int is32) {
    return is32 ? ((const int*)p)[i] : (int)((const long long*)p)[i];
}

__global__ void zero_fill_kernel() {
    int i = blockIdx.x * blockDim.x + threadIdx.x;
    if (i < MTOT) g_fill[i] = 0;
}

// ---------------------------------------------------------
// One-time W hi/lo bf16 split (32768 elements)
// ---------------------------------------------------------
__global__ void wsplit_kernel(const float* __restrict__ w) {
    int i = blockIdx.x * blockDim.x + threadIdx.x;
    if (i < FF * HH) {
        float v = w[i];
        __nv_bfloat16 hi = __float2bfloat16(v);
        g_whi[i] = hi;
        g_wlo[i] = __float2bfloat16(v - __bfloat162float(hi));
    }
}

// ---------------------------------------------------------
// Kernel 1: fused dropout + GEMM via bf16 tensor cores, split precision,
// DOUBLE-BUFFERED smem with register prefetch (one sync per k0 iter).
// xw ~= a_hi*b_hi + a_hi*b_lo + a_lo*b_hi  (fp32 accum, err ~2^-16)
// BM=64, BN=128, BK=32, 256 threads (8 warps, each 32x32 out tile)
// ---------------------------------------------------------
#define A_LD 40
#define B_LD 136
#define S_LD 132

#define LOAD_REGS(K0)                                                        \
    {                                                                        \
        _Pragma("unroll")                                                    \
        for (int r = 0; r < 2; r++) {                                        \
            int i   = tid + r * 256;                                         \
            int row = i >> 3;                                                \
            int col = (i & 7) * 4;                                           \
            size_t gidx = (size_t)(m0 + row) * FF + (K0) + col;              \
            pxv[r] = *(const float4*)(x + gidx);                             \
            puv[r] = *(const float4*)(u + gidx);                             \
            int brow = i >> 4;                                               \
            int bcol = (i & 15) * 8;                                         \
            size_t goff = (size_t)((K0) + brow) * HH + bcol;                 \
            pbh[r] = *(const uint4*)(g_whi + goff);                          \
            pbl[r] = *(const uint4*)(g_wlo + goff);                          \
        }                                                                    \
    }

#define STORE_STAGE(S)                                                       \
    {                                                                        \
        _Pragma("unroll")                                                    \
        for (int r = 0; r < 2; r++) {                                        \
            int i   = tid + r * 256;                                         \
            int row = i >> 3;                                                \
            int col = (i & 7) * 4;                                           \
            float4 xv = pxv[r];                                              \
            float4 uv = puv[r];                                              \
            float xd[4];                                                     \
            xd[0] = (uv.x > 0.5f) ? 2.0f * xv.x : 0.0f;                      \
            xd[1] = (uv.y > 0.5f) ? 2.0f * xv.y : 0.0f;                      \
            xd[2] = (uv.z > 0.5f) ? 2.0f * xv.z : 0.0f;                      \
            xd[3] = (uv.w > 0.5f) ? 2.0f * xv.w : 0.0f;                      \
            __nv_bfloat16 hi[4], lo[4];                                      \
            _Pragma("unroll")                                                \
            for (int c = 0; c < 4; c++) {                                    \
                hi[c] = __float2bfloat16(xd[c]);                             \
                lo[c] = __float2bfloat16(xd[c] - __bfloat162float(hi[c]));   \
            }                                                                \
            *(__nv_bfloat162*)&sm.t.a_hi[S][row][col]     = __nv_bfloat162(hi[0], hi[1]); \
            *(__nv_bfloat162*)&sm.t.a_hi[S][row][col + 2] = __nv_bfloat162(hi[2], hi[3]); \
            *(__nv_bfloat162*)&sm.t.a_lo[S][row][col]     = __nv_bfloat162(lo[0], lo[1]); \
            *(__nv_bfloat162*)&sm.t.a_lo[S][row][col + 2] = __nv_bfloat162(lo[2], lo[3]); \
            int brow = i >> 4;                                               \
            int bcol = (i & 15) * 8;                                         \
            *(uint4*)&sm.t.b_hi[S][brow][bcol] = pbh[r];                     \
            *(uint4*)&sm.t.b_lo[S][brow][bcol] = pbl[r];                     \
        }                                                                    \
    }

#define MMA_STAGE(S)                                                         \
    {                                                                        \
        _Pragma("unroll")                                                    \
        for (int ks = 0; ks < 32; ks += 16) {                                \
            wmma::fragment<wmma::matrix_a, 16, 16, 16, __nv_bfloat16, wmma::row_major> ah[2], al[2]; \
            wmma::fragment<wmma::matrix_b, 16, 16, 16, __nv_bfloat16, wmma::row_major> bh[2], bl[2]; \
            _Pragma("unroll")                                                \
            for (int i = 0; i < 2; i++) {                                    \
                wmma::load_matrix_sync(ah[i], &sm.t.a_hi[S][wm * 32 + i * 16][ks], A_LD); \
                wmma::load_matrix_sync(al[i], &sm.t.a_lo[S][wm * 32 + i * 16][ks], A_LD); \
            }                                                                \
            _Pragma("unroll")                                                \
            for (int j = 0; j < 2; j++) {                                    \
                wmma::load_matrix_sync(bh[j], &sm.t.b_hi[S][ks][wn * 32 + j * 16], B_LD); \
                wmma::load_matrix_sync(bl[j], &sm.t.b_lo[S][ks][wn * 32 + j * 16], B_LD); \
            }                                                                \
            _Pragma("unroll")                                                \
            for (int i = 0; i < 2; i++)                                      \
                _Pragma("unroll")                                            \
                for (int j = 0; j < 2; j++) {                                \
                    wmma::mma_sync(acc[i][j], ah[i], bh[j], acc[i][j]);      \
                    wmma::mma_sync(acc[i][j], ah[i], bl[j], acc[i][j]);      \
                    wmma::mma_sync(acc[i][j], al[i], bh[j], acc[i][j]);      \
                }                                                            \
        }                                                                    \
    }

__global__ __launch_bounds__(256, 2) void gemm_kernel(
    const float* __restrict__ x,
    const float* __restrict__ u)
{
    __shared__ union SM {
        struct {
            __nv_bfloat16 a_hi[2][64][A_LD];
            __nv_bfloat16 a_lo[2][64][A_LD];
            __nv_bfloat16 b_hi[2][32][B_LD];
            __nv_bfloat16 b_lo[2][32][B_LD];
        } t;
        float stage[64][S_LD];
    } sm;

    const int tid = threadIdx.x;
    const int m0  = blockIdx.x * 64;
    const int wid = tid >> 5;
    const int wm  = wid & 1;          // warp row   (2 x 32 rows)
    const int wn  = wid >> 1;         // warp col   (4 x 32 cols)

    wmma::fragment<wmma::accumulator, 16, 16, 16, float> acc[2][2];
#pragma unroll
    for (int i = 0; i < 2; i++)
#pragma unroll
        for (int j = 0; j < 2; j++) wmma::fill_fragment(acc[i][j], 0.0f);

    float4 pxv[2], puv[2];
    uint4  pbh[2], pbl[2];

    // Prologue: tile 0 into regs -> stage 0
    LOAD_REGS(0)
    STORE_STAGE(0)

#pragma unroll
    for (int it = 0; it < 8; it++) {
        __syncthreads();
        if (it < 7) LOAD_REGS((it + 1) * 32)     // LDGs in flight during mma
        MMA_STAGE(it & 1)
        if (it < 7) STORE_STAGE((it + 1) & 1)
    }

    // ---- Epilogue: stage fp32 in smem, convert to fp16, write g_xwh ----
    __syncthreads();
#pragma unroll
    for (int i = 0; i < 2; i++)
#pragma unroll
        for (int j = 0; j < 2; j++)
            wmma::store_matrix_sync(&sm.stage[wm * 32 + i * 16][wn * 32 + j * 16],
                                    acc[i][j], S_LD, wmma::mem_row_major);
    __syncthreads();

    {
        int row = tid >> 2;               // 0..63
        int seg = (tid & 3) * 32;         // 0,32,64,96
        size_t gbase = (size_t)(m0 + row) * HH + seg;
#pragma unroll
        for (int c = 0; c < 32; c += 2) {
            __half2 h = __floats2half2_rn(sm.stage[row][seg + c], sm.stage[row][seg + c + 1]);
            *(__half2*)(g_xwh + gbase + c) = h;
        }
    }
}

// ---------------------------------------------------------
// Bucket: scatter packed (col, val) into fixed-capacity row buckets
// ---------------------------------------------------------
__global__ __launch_bounds__(256) void bucket_kernel(const void* __restrict__ rows,
                                                     const void* __restrict__ cols,
                                                     const float* __restrict__ vals) {
    const int is32 = g_is32;
    const int b    = blockIdx.x / BPB;
    const int base = b * EE + (blockIdx.x % BPB) * (256 * EPT) + threadIdx.x;
#pragma unroll
    for (int k = 0; k < EPT; k++) {
        int i = base + k * 256;
        int r = load_idx(rows, i, is32);
        int c = load_idx(cols, i, is32);
        float v = vals[i];
        int m = b * NN + r;
        int pos = atomicAdd(&g_fill[m], 1);
        if (pos < CAP)
            g_edge[(size_t)m * CAP + pos] = make_int2(c, __float_as_int(v));
    }
}

// ---------------------------------------------------------
// Gather SpMM: 1 warp per output row, shuffle-broadcast edges.
// Each lane covers 4 h values (one int2 = 4 halves of the fp16 xw row).
// ---------------------------------------------------------
__global__ __launch_bounds__(128) void gather_kernel(float* __restrict__ out)
{
    const int wid  = threadIdx.x >> 5;
    const int lane = threadIdx.x & 31;
    const int m = blockIdx.x * 4 + wid;          // 0..79999
    const int b = m / NN;
    const int cnt = min(g_fill[m], CAP);
    const int2* __restrict__ ebase = g_edge + (size_t)m * CAP;
    const int2* __restrict__ xwb   = (const int2*)g_xwh + (size_t)b * NN * 32;

    float4 acc = make_float4(0.f, 0.f, 0.f, 0.f);

    for (int c0 = 0; c0 < cnt; c0 += 32) {
        int idx = c0 + lane;
        int2 e = (idx < cnt) ? ebase[idx] : make_int2(0, 0);
        int len = min(32, cnt - c0);
        int j = 0;
        for (; j + 4 <= len; j += 4) {
            int   c0i = __shfl_sync(0xffffffffu, e.x, j + 0);
            int   c1i = __shfl_sync(0xffffffffu, e.x, j + 1);
            int   c2i = __shfl_sync(0xffffffffu, e.x, j + 2);
            int   c3i = __shfl_sync(0xffffffffu, e.x, j + 3);
            float v0 = __int_as_float(__shfl_sync(0xffffffffu, e.y, j + 0));
            float v1 = __int_as_float(__shfl_sync(0xffffffffu, e.y, j + 1));
            float v2 = __int_as_float(__shfl_sync(0xffffffffu, e.y, j + 2));
            float v3 = __int_as_float(__shfl_sync(0xffffffffu, e.y, j + 3));
            int2 w0 = xwb[(size_t)c0i * 32 + lane];
            int2 w1 = xwb[(size_t)c1i * 32 + lane];
            int2 w2 = xwb[(size_t)c2i * 32 + lane];
            int2 w3 = xwb[(size_t)c3i * 32 + lane];
            float2 a0 = __half22float2(*(__half2*)&w0.x), b0 = __half22float2(*(__half2*)&w0.y);
            float2 a1 = __half22float2(*(__half2*)&w1.x), b1 = __half22float2(*(__half2*)&w1.y);
            float2 a2 = __half22float2(*(__half2*)&w2.x), b2 = __half22float2(*(__half2*)&w2.y);
            float2 a3 = __half22float2(*(__half2*)&w3.x), b3 = __half22float2(*(__half2*)&w3.y);
            acc.x += v0 * a0.x + v1 * a1.x + v2 * a2.x + v3 * a3.x;
            acc.y += v0 * a0.y + v1 * a1.y + v2 * a2.y + v3 * a3.y;
            acc.z += v0 * b0.x + v1 * b1.x + v2 * b2.x + v3 * b3.x;
            acc.w += v0 * b0.y + v1 * b1.y + v2 * b2.y + v3 * b3.y;
        }
        for (; j < len; j++) {
            int   ci = __shfl_sync(0xffffffffu, e.x, j);
            float v  = __int_as_float(__shfl_sync(0xffffffffu, e.y, j));
            int2 wv = xwb[(size_t)ci * 32 + lane];
            float2 a  = __half22float2(*(__half2*)&wv.x);
            float2 bb = __half22float2(*(__half2*)&wv.y);
            acc.x += v * a.x;  acc.y += v * a.y;
            acc.z += v * bb.x; acc.w += v * bb.y;
        }
    }
    ((float4*)out)[(size_t)m * 32 + lane] = acc;
}

// ---------------------------------------------------------
extern "C" void kernel_launch(void* const* d_in, const int* in_sizes, int n_in,
                              void* d_out, int out_size)
{
    const float* x    = (const float*)d_in[0];
    const float* u    = (const float*)d_in[1];
    const void*  rows = d_in[2];
    const void*  cols = d_in[3];
    const float* vals = (const float*)d_in[4];
    const float* w    = (const float*)d_in[5];
    float*       out  = (float*)d_out;

    detect_kernel<<<1, 32>>>(rows);
    zero_fill_kernel<<<(MTOT + 255) / 256, 256>>>();
    wsplit_kernel<<<(FF * HH + 255) / 256, 256>>>(w);

    gemm_kernel<<<MTOT / 64, 256>>>(x, u);
    bucket_kernel<<<BB * BPB, 256>>>(rows, cols, vals);

    gather_kernel<<<MTOT / 4, 128>>>(out);
}